// round 1
// baseline (speedup 1.0000x reference)
#include <cuda_runtime.h>
#include <math.h>

#define N_      16
#define C_      128
#define T_      16384
#define K_      64
#define KG_     73      // clusters + ghosts
#define K2_     80      // padded cluster rows for GEMM1 tiling
#define TC_     64      // t-tile width
#define SLICES_ 37      // t-slices per n  (16 x 37 = 592 CTAs = 2.0 waves @ 2 CTA/SM)
#define TILES_  (T_ / TC_)   // 256 tiles per n
#define LGT_    65      // logits row stride (odd -> conflict-free columns)
#define EPSF    1e-12f

// Per-slice partials (written once per CTA, no atomics -> deterministic)
__device__ float g_vlad_part[SLICES_ * N_ * K_ * C_];   // ~19.4 MB
__device__ float g_asum_part[SLICES_ * N_ * K_];

// Shared layout (floats): ws[80*128] | xs[64*128 swizzled] | lg[80*65] | sninv[64] | snrm[64]
#define SMEM_FLOATS (K2_*C_ + TC_*C_ + K2_*LGT_ + TC_ + TC_)

__global__ __launch_bounds__(256, 2)
void vlad_main(const float* __restrict__ x, const float* __restrict__ conv_w) {
    const int n   = blockIdx.x;
    const int sl  = blockIdx.y;
    const int tid = threadIdx.x;

    extern __shared__ float sm[];
    float* ws    = sm;                       // [K2_][C_]
    float* xs    = ws + K2_ * C_;            // [TC_][C_] swizzled
    float* lg    = xs + TC_ * C_;            // [K2_][LGT_]
    float* sninv = lg + K2_ * LGT_;          // 1/max(||x_t||,eps)
    float* snrm  = sninv + TC_;              // max(||x_t||,eps)

    // Load conv_w (73x128), zero-pad rows 73..79
    for (int i = tid; i < K2_ * C_; i += 256)
        ws[i] = (i < KG_ * C_) ? conv_w[i] : 0.f;

    const int ty = tid >> 4;    // 0..15
    const int tx = tid & 15;    // 0..15

    // Register-resident VLAD accumulator: k = 4*ty+i, c = 8*tx+j
    float acc[4][8];
#pragma unroll
    for (int i = 0; i < 4; ++i)
#pragma unroll
        for (int j = 0; j < 8; ++j) acc[i][j] = 0.f;
    float asum = 0.f;   // meaningful for tid < 64 (k = tid)

    const float* xbase = x + (long)n * C_ * T_;

    for (int tile = sl; tile < TILES_; tile += SLICES_) {
        const int t0 = tile * TC_;
        __syncthreads();   // previous tile's consumers done before overwriting xs/lg

        // ---- Load x tile -> xs, swizzled: phys f4 col = (c4 + (t>>2)) & 31 ----
#pragma unroll
        for (int j = 0; j < 8; ++j) {
            int lin = tid + 256 * j;            // 0..2047
            int c   = lin >> 4;                 // 0..127
            int t4  = lin & 15;                 // 0..15  (t = 4*t4 + e, t>>2 = t4)
            float4 v = *((const float4*)(xbase + (long)c * T_ + t0) + t4);
            int c4 = c >> 2, ce = c & 3;
            int col = (((c4 + t4) & 31) << 2) + ce;
            float* row = xs + (4 * t4) * C_;
            row[0 * C_ + col] = v.x;
            row[1 * C_ + col] = v.y;
            row[2 * C_ + col] = v.z;
            row[3 * C_ + col] = v.w;
        }
        __syncthreads();

        // ---- Column L2 norms (4 threads per t) ----
        {
            int t = tid >> 2, part = tid & 3;
            int rot = t >> 2;
            const float4* row = (const float4*)(xs + t * C_);
            float ss = 0.f;
#pragma unroll
            for (int i = 0; i < 8; ++i) {
                float4 v = row[(part + 4 * i + rot) & 31];
                ss += v.x * v.x + v.y * v.y + v.z * v.z + v.w * v.w;
            }
            ss += __shfl_xor_sync(0xffffffffu, ss, 1);
            ss += __shfl_xor_sync(0xffffffffu, ss, 2);
            if (part == 0) {
                float nr = fmaxf(sqrtf(ss), EPSF);
                snrm[t]  = nr;
                sninv[t] = 1.f / nr;
            }
        }

        // ---- GEMM1: lg[k][t] = sum_c W[k][c] * x[t][c]   (raw x; norm folded later) ----
        {
            const int k0 = ty * 5, tt0 = tx * 4;           // (tt0+j)>>2 == tx
            float r[5][4];
#pragma unroll
            for (int i = 0; i < 5; ++i)
#pragma unroll
                for (int j = 0; j < 4; ++j) r[i][j] = 0.f;

            const float4* wp  = (const float4*)ws;                 // [K2_][32]
            const float4* xp4 = (const float4*)(xs + tt0 * C_);    // 4 rows x 32
#pragma unroll 2
            for (int c4 = 0; c4 < 32; ++c4) {
                int bi = (c4 + tx) & 31;
                float4 b0 = xp4[0 * 32 + bi];
                float4 b1 = xp4[1 * 32 + bi];
                float4 b2 = xp4[2 * 32 + bi];
                float4 b3 = xp4[3 * 32 + bi];
#pragma unroll
                for (int i = 0; i < 5; ++i) {
                    float4 a = wp[(k0 + i) * 32 + c4];
                    r[i][0] += a.x * b0.x + a.y * b0.y + a.z * b0.z + a.w * b0.w;
                    r[i][1] += a.x * b1.x + a.y * b1.y + a.z * b1.z + a.w * b1.w;
                    r[i][2] += a.x * b2.x + a.y * b2.y + a.z * b2.z + a.w * b2.w;
                    r[i][3] += a.x * b3.x + a.y * b3.y + a.z * b3.z + a.w * b3.w;
                }
            }
#pragma unroll
            for (int i = 0; i < 5; ++i)
#pragma unroll
                for (int j = 0; j < 4; ++j)
                    lg[(k0 + i) * LGT_ + tt0 + j] = r[i][j];
        }
        __syncthreads();

        // ---- Softmax per column t over 73 logits; store soft * (1/||x_t||) for k<64 ----
        if (tid < TC_) {
            const int t = tid;
            float m = -1e30f;
            for (int k = 0; k < KG_; ++k) m = fmaxf(m, lg[k * LGT_ + t]);
            const float inv = sninv[t];
            float s = 0.f;
            for (int k = 0; k < KG_; ++k) {
                float e = __expf((lg[k * LGT_ + t] - m) * inv);
                s += e;
                if (k < K_) lg[k * LGT_ + t] = e;
            }
            const float scale = inv / s;
            for (int k = 0; k < K_; ++k) lg[k * LGT_ + t] *= scale;
        }
        __syncthreads();

        // ---- a_sum (unscaled soft): soft = lg_scaled * ||x_t|| ----
        if (tid < K_) {
            float s = 0.f;
            for (int t = 0; t < TC_; ++t) s += lg[tid * LGT_ + t] * snrm[t];
            asum += s;
        }

        // ---- GEMM2: acc[k][c] += soft_scaled[k][t] * x[t][c]  (== soft * xn) ----
        {
            const int k0 = ty * 4, c8 = tx * 2;   // f4 column base
#pragma unroll 2
            for (int t = 0; t < TC_; ++t) {
                const int rot = t >> 2;
                const float4* row = (const float4*)(xs + t * C_);
                float4 b0 = row[(c8 + rot) & 31];
                float4 b1 = row[(c8 + 1 + rot) & 31];
                float s0 = lg[(k0 + 0) * LGT_ + t];
                float s1 = lg[(k0 + 1) * LGT_ + t];
                float s2 = lg[(k0 + 2) * LGT_ + t];
                float s3 = lg[(k0 + 3) * LGT_ + t];
                acc[0][0] += s0 * b0.x; acc[0][1] += s0 * b0.y; acc[0][2] += s0 * b0.z; acc[0][3] += s0 * b0.w;
                acc[0][4] += s0 * b1.x; acc[0][5] += s0 * b1.y; acc[0][6] += s0 * b1.z; acc[0][7] += s0 * b1.w;
                acc[1][0] += s1 * b0.x; acc[1][1] += s1 * b0.y; acc[1][2] += s1 * b0.z; acc[1][3] += s1 * b0.w;
                acc[1][4] += s1 * b1.x; acc[1][5] += s1 * b1.y; acc[1][6] += s1 * b1.z; acc[1][7] += s1 * b1.w;
                acc[2][0] += s2 * b0.x; acc[2][1] += s2 * b0.y; acc[2][2] += s2 * b0.z; acc[2][3] += s2 * b0.w;
                acc[2][4] += s2 * b1.x; acc[2][5] += s2 * b1.y; acc[2][6] += s2 * b1.z; acc[2][7] += s2 * b1.w;
                acc[3][0] += s3 * b0.x; acc[3][1] += s3 * b0.y; acc[3][2] += s3 * b0.z; acc[3][3] += s3 * b0.w;
                acc[3][4] += s3 * b1.x; acc[3][5] += s3 * b1.y; acc[3][6] += s3 * b1.z; acc[3][7] += s3 * b1.w;
            }
        }
    }

    // ---- Write per-slice partials ----
    float* gp = g_vlad_part + ((long)(sl * N_ + n)) * K_ * C_;
#pragma unroll
    for (int i = 0; i < 4; ++i) {
        float4 o0 = make_float4(acc[i][0], acc[i][1], acc[i][2], acc[i][3]);
        float4 o1 = make_float4(acc[i][4], acc[i][5], acc[i][6], acc[i][7]);
        float* dst = gp + (ty * 4 + i) * C_ + tx * 8;
        ((float4*)dst)[0] = o0;
        ((float4*)dst)[1] = o1;
    }
    if (tid < K_)
        g_asum_part[((long)(sl * N_ + n)) * K_ + tid] = asum;
}

// ---- Epilogue: reduce slices, centroid subtract, intra-norm, cw scale, global norm ----
__global__ void vlad_epilogue(const float* __restrict__ centroids,
                              const float* __restrict__ cwts,
                              float* __restrict__ out) {
    const int n = blockIdx.x, tid = threadIdx.x;
    const int w = tid >> 5, lane = tid & 31;

    __shared__ float buf[K_ * C_];
    __shared__ float sasum[K_];
    __shared__ float wss[8];
    __shared__ float scw;     // 1/max(||cw||,eps)
    __shared__ float sginv;   // 1/max(||v||,eps)

    if (tid < K_) {
        float s = 0.f;
        for (int sl = 0; sl < SLICES_; ++sl)
            s += g_asum_part[((long)(sl * N_ + n)) * K_ + tid];
        sasum[tid] = s;
    }
    if (tid == 0) {
        float s = 0.f;
        for (int k = 0; k < K_; ++k) s += cwts[k] * cwts[k];
        scw = 1.f / fmaxf(sqrtf(s), EPSF);
    }
    __syncthreads();

    float lss = 0.f;
    for (int k = w; k < K_; k += 8) {
        float4 v = make_float4(0.f, 0.f, 0.f, 0.f);
        for (int sl = 0; sl < SLICES_; ++sl) {
            const float4 p = ((const float4*)(g_vlad_part +
                              ((long)(sl * N_ + n)) * K_ * C_ + k * C_))[lane];
            v.x += p.x; v.y += p.y; v.z += p.z; v.w += p.w;
        }
        const float a = sasum[k];
        const float4 ce = ((const float4*)(centroids + k * C_))[lane];
        v.x -= a * ce.x; v.y -= a * ce.y; v.z -= a * ce.z; v.w -= a * ce.w;

        float ssp = v.x * v.x + v.y * v.y + v.z * v.z + v.w * v.w;  // per-lane partial
        float sst = ssp;
        sst += __shfl_xor_sync(0xffffffffu, sst, 16);
        sst += __shfl_xor_sync(0xffffffffu, sst, 8);
        sst += __shfl_xor_sync(0xffffffffu, sst, 4);
        sst += __shfl_xor_sync(0xffffffffu, sst, 2);
        sst += __shfl_xor_sync(0xffffffffu, sst, 1);

        const float scale = (1.f / fmaxf(sqrtf(sst), EPSF)) * cwts[k] * scw;
        v.x *= scale; v.y *= scale; v.z *= scale; v.w *= scale;
        ((float4*)(buf + k * C_))[lane] = v;
        lss += ssp * scale * scale;   // own-lane contribution to ||v||^2
    }

    // reduce lss
    lss += __shfl_xor_sync(0xffffffffu, lss, 16);
    lss += __shfl_xor_sync(0xffffffffu, lss, 8);
    lss += __shfl_xor_sync(0xffffffffu, lss, 4);
    lss += __shfl_xor_sync(0xffffffffu, lss, 2);
    lss += __shfl_xor_sync(0xffffffffu, lss, 1);
    if (lane == 0) wss[w] = lss;
    __syncthreads();
    if (tid == 0) {
        float g = 0.f;
        for (int i = 0; i < 8; ++i) g += wss[i];
        sginv = 1.f / fmaxf(sqrtf(g), EPSF);
    }
    __syncthreads();

    const float gi = sginv;
    float4* outp = (float4*)(out + (long)n * K_ * C_);
    const float4* bp = (const float4*)buf;
    for (int i = tid; i < (K_ * C_) / 4; i += 256) {
        float4 v = bp[i];
        v.x *= gi; v.y *= gi; v.z *= gi; v.w *= gi;
        outp[i] = v;
    }
}

extern "C" void kernel_launch(void* const* d_in, const int* in_sizes, int n_in,
                              void* d_out, int out_size) {
    const float* x      = (const float*)d_in[0];
    const float* conv_w = (const float*)d_in[1];
    const float* cent   = (const float*)d_in[2];
    const float* cwts   = (const float*)d_in[3];
    float* out = (float*)d_out;

    const size_t smem = SMEM_FLOATS * sizeof(float);   // ~95 KB
    cudaFuncSetAttribute(vlad_main, cudaFuncAttributeMaxDynamicSharedMemorySize, (int)smem);

    vlad_main<<<dim3(N_, SLICES_), 256, smem>>>(x, conv_w);
    vlad_epilogue<<<N_, 256>>>(cent, cwts, out);
}

// round 2
// speedup vs baseline: 1.0660x; 1.0660x over previous
#include <cuda_runtime.h>
#include <math.h>

#define N_      16
#define C_      128
#define T_      16384
#define K_      64
#define KG_     73      // clusters + ghosts
#define K2_     80      // padded cluster rows for GEMM1 tiling
#define TC_     64      // t-tile width
#define SLICES_ 37      // 16 x 37 = 592 CTAs = 2.0 waves @ 2 CTA/SM
#define TILES_  (T_ / TC_)
#define LGT_    65
#define EPSF    1e-12f

__device__ float g_vlad_part[SLICES_ * N_ * K_ * C_];   // ~19.4 MB
__device__ float g_asum_part[SLICES_ * N_ * K_];
__device__ float g_knorm[N_ * K_];

#define SMEM_FLOATS (K2_*C_ + TC_*C_ + K2_*LGT_ + TC_ + TC_)

// Packed dual-FMA: d = a*b + c elementwise on float2 (SASS FFMA2; ptxas won't emit it from C++)
__device__ __forceinline__ float2 ffma2(float2 a, float2 b, float2 c) {
    float2 d;
    asm("fma.rn.f32x2 %0, %1, %2, %3;"
        : "=l"(*(unsigned long long*)&d)
        : "l"(*(unsigned long long*)&a),
          "l"(*(unsigned long long*)&b),
          "l"(*(unsigned long long*)&c));
    return d;
}

__global__ __launch_bounds__(256, 2)
void vlad_main(const float* __restrict__ x, const float* __restrict__ conv_w) {
    const int n   = blockIdx.x;
    const int sl  = blockIdx.y;
    const int tid = threadIdx.x;

    extern __shared__ float sm[];
    float* ws    = sm;                       // [K2_][C_]
    float* xs    = ws + K2_ * C_;            // [TC_][C_] swizzled
    float* lg    = xs + TC_ * C_;            // [K2_][LGT_]
    float* sninv = lg + K2_ * LGT_;
    float* snrm  = sninv + TC_;

    for (int i = tid; i < K2_ * C_; i += 256)
        ws[i] = (i < KG_ * C_) ? conv_w[i] : 0.f;

    const int ty = tid >> 4;    // 0..15
    const int tx = tid & 15;    // 0..15

    // Register-resident VLAD accumulator: k = 4*ty+i, c-pair = tx*8 + 2*j
    float2 acc2[4][4];
#pragma unroll
    for (int i = 0; i < 4; ++i)
#pragma unroll
        for (int j = 0; j < 4; ++j) acc2[i][j] = make_float2(0.f, 0.f);
    float asum = 0.f;   // k = tid>>2 (4-way replicated)

    const float* xbase = x + (long)n * C_ * T_;

    for (int tile = sl; tile < TILES_; tile += SLICES_) {
        const int t0 = tile * TC_;
        __syncthreads();

        // ---- Load x tile -> xs, swizzled: phys f4 col = (c4 + (t>>2)) & 31 ----
#pragma unroll
        for (int j = 0; j < 8; ++j) {
            int lin = tid + 256 * j;
            int c   = lin >> 4;
            int t4  = lin & 15;
            float4 v = *((const float4*)(xbase + (long)c * T_ + t0) + t4);
            int c4 = c >> 2, ce = c & 3;
            int col = (((c4 + t4) & 31) << 2) + ce;
            float* row = xs + (4 * t4) * C_;
            row[0 * C_ + col] = v.x;
            row[1 * C_ + col] = v.y;
            row[2 * C_ + col] = v.z;
            row[3 * C_ + col] = v.w;
        }
        __syncthreads();

        // ---- Column L2 norms (4 threads per t) ----
        {
            int t = tid >> 2, part = tid & 3;
            int rot = t >> 2;
            const float4* row = (const float4*)(xs + t * C_);
            float ss = 0.f;
#pragma unroll
            for (int i = 0; i < 8; ++i) {
                float4 v = row[(part + 4 * i + rot) & 31];
                ss += v.x * v.x + v.y * v.y + v.z * v.z + v.w * v.w;
            }
            ss += __shfl_xor_sync(0xffffffffu, ss, 1);
            ss += __shfl_xor_sync(0xffffffffu, ss, 2);
            if (part == 0) {
                float nr = fmaxf(sqrtf(ss), EPSF);
                snrm[t]  = nr;
                sninv[t] = 1.f / nr;
            }
        }

        // ---- GEMM1 (FFMA2): lg[k][t] = sum_c W[k][c] * x[t][c] ----
        {
            const int k0 = ty * 5, tt0 = tx * 4;
            float2 r2[5][4];
#pragma unroll
            for (int i = 0; i < 5; ++i)
#pragma unroll
                for (int j = 0; j < 4; ++j) r2[i][j] = make_float2(0.f, 0.f);

            const float4* wp  = (const float4*)ws;
            const float4* xp4 = (const float4*)(xs + tt0 * C_);
#pragma unroll 2
            for (int c4 = 0; c4 < 32; ++c4) {
                int bi = (c4 + tx) & 31;
                float4 b0 = xp4[0 * 32 + bi];
                float4 b1 = xp4[1 * 32 + bi];
                float4 b2 = xp4[2 * 32 + bi];
                float4 b3 = xp4[3 * 32 + bi];
                const float2* b0p = (const float2*)&b0;
                const float2* b1p = (const float2*)&b1;
                const float2* b2p = (const float2*)&b2;
                const float2* b3p = (const float2*)&b3;
#pragma unroll
                for (int i = 0; i < 5; ++i) {
                    float4 a = wp[(k0 + i) * 32 + c4];
                    const float2* ap = (const float2*)&a;
                    r2[i][0] = ffma2(ap[0], b0p[0], r2[i][0]);
                    r2[i][0] = ffma2(ap[1], b0p[1], r2[i][0]);
                    r2[i][1] = ffma2(ap[0], b1p[0], r2[i][1]);
                    r2[i][1] = ffma2(ap[1], b1p[1], r2[i][1]);
                    r2[i][2] = ffma2(ap[0], b2p[0], r2[i][2]);
                    r2[i][2] = ffma2(ap[1], b2p[1], r2[i][2]);
                    r2[i][3] = ffma2(ap[0], b3p[0], r2[i][3]);
                    r2[i][3] = ffma2(ap[1], b3p[1], r2[i][3]);
                }
            }
#pragma unroll
            for (int i = 0; i < 5; ++i)
#pragma unroll
                for (int j = 0; j < 4; ++j)
                    lg[(k0 + i) * LGT_ + tt0 + j] = r2[i][j].x + r2[i][j].y;
        }
        __syncthreads();

        // ---- Softmax per column t over 73 logits (4 threads per t) ----
        {
            const int t = tid >> 2, part = tid & 3;
            float m = -1e30f;
            for (int k = part; k < KG_; k += 4) m = fmaxf(m, lg[k * LGT_ + t]);
            m = fmaxf(m, __shfl_xor_sync(0xffffffffu, m, 1));
            m = fmaxf(m, __shfl_xor_sync(0xffffffffu, m, 2));
            const float inv = sninv[t];
            float s = 0.f;
            for (int k = part; k < KG_; k += 4) {
                float e = __expf((lg[k * LGT_ + t] - m) * inv);
                s += e;
                if (k < K_) lg[k * LGT_ + t] = e;
            }
            s += __shfl_xor_sync(0xffffffffu, s, 1);
            s += __shfl_xor_sync(0xffffffffu, s, 2);
            const float scale = inv / s;
            for (int k = part; k < K_; k += 4) lg[k * LGT_ + t] *= scale;
        }
        __syncthreads();

        // ---- a_sum: soft = lg_scaled * ||x_t||  (4 threads per k) ----
        {
            const int k = tid >> 2, part = tid & 3;
            float s = 0.f;
            for (int t = part; t < TC_; t += 4) s += lg[k * LGT_ + t] * snrm[t];
            s += __shfl_xor_sync(0xffffffffu, s, 1);
            s += __shfl_xor_sync(0xffffffffu, s, 2);
            asum += s;
        }

        // ---- GEMM2 (FFMA2): acc[k][c] += soft_scaled[k][t] * x[t][c] ----
        {
            const int k0 = ty * 4, c8 = tx * 2;
#pragma unroll 2
            for (int t = 0; t < TC_; ++t) {
                const int rot = t >> 2;
                const float4* row = (const float4*)(xs + t * C_);
                float4 b0 = row[(c8 + rot) & 31];
                float4 b1 = row[(c8 + 1 + rot) & 31];
                const float2* b0p = (const float2*)&b0;
                const float2* b1p = (const float2*)&b1;
                float2 s0 = make_float2(lg[(k0 + 0) * LGT_ + t], lg[(k0 + 0) * LGT_ + t]);
                float2 s1 = make_float2(lg[(k0 + 1) * LGT_ + t], lg[(k0 + 1) * LGT_ + t]);
                float2 s2 = make_float2(lg[(k0 + 2) * LGT_ + t], lg[(k0 + 2) * LGT_ + t]);
                float2 s3 = make_float2(lg[(k0 + 3) * LGT_ + t], lg[(k0 + 3) * LGT_ + t]);
                acc2[0][0] = ffma2(s0, b0p[0], acc2[0][0]);
                acc2[0][1] = ffma2(s0, b0p[1], acc2[0][1]);
                acc2[0][2] = ffma2(s0, b1p[0], acc2[0][2]);
                acc2[0][3] = ffma2(s0, b1p[1], acc2[0][3]);
                acc2[1][0] = ffma2(s1, b0p[0], acc2[1][0]);
                acc2[1][1] = ffma2(s1, b0p[1], acc2[1][1]);
                acc2[1][2] = ffma2(s1, b1p[0], acc2[1][2]);
                acc2[1][3] = ffma2(s1, b1p[1], acc2[1][3]);
                acc2[2][0] = ffma2(s2, b0p[0], acc2[2][0]);
                acc2[2][1] = ffma2(s2, b0p[1], acc2[2][1]);
                acc2[2][2] = ffma2(s2, b1p[0], acc2[2][2]);
                acc2[2][3] = ffma2(s2, b1p[1], acc2[2][3]);
                acc2[3][0] = ffma2(s3, b0p[0], acc2[3][0]);
                acc2[3][1] = ffma2(s3, b0p[1], acc2[3][1]);
                acc2[3][2] = ffma2(s3, b1p[0], acc2[3][2]);
                acc2[3][3] = ffma2(s3, b1p[1], acc2[3][3]);
            }
        }
    }

    // ---- Write per-slice partials ----
    float* gp = g_vlad_part + ((long)(sl * N_ + n)) * K_ * C_;
#pragma unroll
    for (int i = 0; i < 4; ++i) {
        float4 o0 = make_float4(acc2[i][0].x, acc2[i][0].y, acc2[i][1].x, acc2[i][1].y);
        float4 o1 = make_float4(acc2[i][2].x, acc2[i][2].y, acc2[i][3].x, acc2[i][3].y);
        float* dst = gp + (ty * 4 + i) * C_ + tx * 8;
        ((float4*)dst)[0] = o0;
        ((float4*)dst)[1] = o1;
    }
    if ((tid & 3) == 0)
        g_asum_part[((long)(sl * N_ + n)) * K_ + (tid >> 2)] = asum;
}

// ---- Reduce: one CTA per (n,k). Slice sum, centroid subtract, intra-norm, cw scale ----
__global__ __launch_bounds__(128)
void vlad_reduce(const float* __restrict__ centroids,
                 const float* __restrict__ cwts,
                 float* __restrict__ out) {
    const int k = blockIdx.x, n = blockIdx.y;
    const int tid = threadIdx.x;  // 128, one channel each

    __shared__ float red[128];
    __shared__ float scw;

    // slice-sum of vlad partials for channel tid
    float v = 0.f;
    const float* base = g_vlad_part + (long)n * K_ * C_ + (long)k * C_ + tid;
    const long   str  = (long)N_ * K_ * C_;
#pragma unroll 4
    for (int sl = 0; sl < SLICES_; ++sl) v += base[sl * str];

    // asum reduce (37 values, padded with zeros)
    red[tid] = (tid < SLICES_) ? g_asum_part[((long)(tid * N_ + n)) * K_ + k] : 0.f;
    if (tid == 0) {
        float s = 0.f;
        for (int kk = 0; kk < K_; ++kk) s += cwts[kk] * cwts[kk];
        scw = 1.f / fmaxf(sqrtf(s), EPSF);
    }
    __syncthreads();
#pragma unroll
    for (int s = 64; s > 0; s >>= 1) {
        if (tid < s) red[tid] += red[tid + s];
        __syncthreads();
    }
    const float asumv = red[0];
    __syncthreads();

    v -= asumv * centroids[k * C_ + tid];

    // squared-sum block reduce
    red[tid] = v * v;
    __syncthreads();
#pragma unroll
    for (int s = 64; s > 0; s >>= 1) {
        if (tid < s) red[tid] += red[tid + s];
        __syncthreads();
    }
    const float ssq = red[0];

    const float scale = (1.f / fmaxf(sqrtf(ssq), EPSF)) * cwts[k] * scw;
    out[(long)n * K_ * C_ + (long)k * C_ + tid] = v * scale;
    if (tid == 0) g_knorm[n * K_ + k] = ssq * scale * scale;
}

// ---- Finalize: global L2 norm per sample ----
__global__ __launch_bounds__(256)
void vlad_finalize(float* __restrict__ out) {
    const int n = blockIdx.x, tid = threadIdx.x;
    __shared__ float sginv;
    if (tid == 0) {
        float g = 0.f;
        for (int k = 0; k < K_; ++k) g += g_knorm[n * K_ + k];
        sginv = 1.f / fmaxf(sqrtf(g), EPSF);
    }
    __syncthreads();
    const float gi = sginv;
    float4* p = (float4*)(out + (long)n * K_ * C_);
    for (int i = tid; i < (K_ * C_) / 4; i += 256) {
        float4 v = p[i];
        v.x *= gi; v.y *= gi; v.z *= gi; v.w *= gi;
        p[i] = v;
    }
}

extern "C" void kernel_launch(void* const* d_in, const int* in_sizes, int n_in,
                              void* d_out, int out_size) {
    const float* x      = (const float*)d_in[0];
    const float* conv_w = (const float*)d_in[1];
    const float* cent   = (const float*)d_in[2];
    const float* cwts   = (const float*)d_in[3];
    float* out = (float*)d_out;

    const size_t smem = SMEM_FLOATS * sizeof(float);   // ~93 KB
    cudaFuncSetAttribute(vlad_main, cudaFuncAttributeMaxDynamicSharedMemorySize, (int)smem);

    vlad_main<<<dim3(N_, SLICES_), 256, smem>>>(x, conv_w);
    vlad_reduce<<<dim3(K_, N_), 128>>>(cent, cwts, out);
    vlad_finalize<<<N_, 256>>>(out);
}

// round 4
// speedup vs baseline: 2.7248x; 2.5561x over previous
#include <cuda_runtime.h>
#include <cuda_bf16.h>
#include <math.h>
#include <cstdint>

#define N_      16
#define C_      128
#define T_      16384
#define K_      64
#define KG_     73
#define TT_     128
#define TILES_  (T_ / TT_)   // 128
#define SL_     9            // 16*9 = 144 CTAs, 1/SM
#define EPSF    1e-12f

__device__ float g_vlad_part[SL_ * N_ * K_ * C_];
__device__ float g_asum_part[SL_ * N_ * K_];
__device__ float g_knorm[N_ * K_];

// ---- smem layout (bytes) ----
#define XS_HI   0        // x hi  [c=128][t=128] bf16, 256B rows, swizzled
#define XS_LO   32768
#define W_HI    65536    // W hi [k=80][c=128] bf16 (rows 73..79 zero)
#define W_LO    86016
#define SF_HI   106496   // soft hi [t=128][k=64] bf16, 128B rows, swizzled
#define SF_LO   122880
#define NRMP    139264   // float [8][128]
#define SNINV   143360   // float [128]
#define ASW     143872   // float [8][64]
#define SMEM_SZ 145920

// ldmatrix x4 (non-trans): B-fragments from [n][k] row-major storage
__device__ __forceinline__ void ldsm4(uint32_t a, uint32_t r[4]) {
    asm volatile("ldmatrix.sync.aligned.m8n8.x4.shared.b16 {%0,%1,%2,%3}, [%4];"
        : "=r"(r[0]), "=r"(r[1]), "=r"(r[2]), "=r"(r[3]) : "r"(a));
}
// ldmatrix x4 trans: A-fragments from [k][m] (col-major A) storage
__device__ __forceinline__ void ldsm4t(uint32_t a, uint32_t r[4]) {
    asm volatile("ldmatrix.sync.aligned.m8n8.x4.trans.shared.b16 {%0,%1,%2,%3}, [%4];"
        : "=r"(r[0]), "=r"(r[1]), "=r"(r[2]), "=r"(r[3]) : "r"(a));
}
// D += A*B, m16n8k16 bf16 -> f32
__device__ __forceinline__ void mma16816(float d[4], const uint32_t a[4], const uint32_t b[2]) {
    asm volatile("mma.sync.aligned.m16n8k16.row.col.f32.bf16.bf16.f32 "
        "{%0,%1,%2,%3}, {%4,%5,%6,%7}, {%8,%9}, {%0,%1,%2,%3};"
        : "+f"(d[0]), "+f"(d[1]), "+f"(d[2]), "+f"(d[3])
        : "r"(a[0]), "r"(a[1]), "r"(a[2]), "r"(a[3]), "r"(b[0]), "r"(b[1]));
}
// lane address for both ldsm recipes (A-trans and B share the group pattern)
__device__ __forceinline__ uint32_t ldsm_addr(uint32_t base, int row0, int colb0, int rs, int lane) {
    int g = lane >> 3, r = lane & 7;
    int row  = row0 + r + ((g & 2) << 2);
    int colb = colb0 + ((g & 1) << 4);
    return base + row * rs + (colb ^ ((row & 7) << 4));
}

__device__ __forceinline__ void hilo2(float z0, float z1, uint32_t& hw, uint32_t& lw) {
    __nv_bfloat16 h0 = __float2bfloat16(z0);
    __nv_bfloat16 h1 = __float2bfloat16(z1);
    __nv_bfloat16 l0 = __float2bfloat16(z0 - __bfloat162float(h0));
    __nv_bfloat16 l1 = __float2bfloat16(z1 - __bfloat162float(h1));
    hw = (uint32_t)__bfloat16_as_ushort(h0) | ((uint32_t)__bfloat16_as_ushort(h1) << 16);
    lw = (uint32_t)__bfloat16_as_ushort(l0) | ((uint32_t)__bfloat16_as_ushort(l1) << 16);
}

__global__ __launch_bounds__(256, 1)
void vlad_mma(const float* __restrict__ x, const float* __restrict__ conv_w) {
    extern __shared__ __align__(16) char smem[];
    uint32_t sb;
    asm("{ .reg .u64 t; cvta.to.shared.u64 t, %1; cvt.u32.u64 %0, t; }" : "=r"(sb) : "l"(smem));

    const int n = blockIdx.x, sl = blockIdx.y;
    const int tid = threadIdx.x, w = tid >> 5, lane = tid & 31;
    const int q = lane >> 2, qk = lane & 3;

    float* nrmp    = (float*)(smem + NRMP);
    float* sninv_s = (float*)(smem + SNINV);
    float* asw     = (float*)(smem + ASW);

    // ---- W -> smem hi/lo, swizzled [k=80][c=128], rows >= 73 zero ----
    for (int idx = tid; idx < 80 * 128; idx += 256) {
        int k = idx >> 7, c = idx & 127;
        float v = (k < KG_) ? conv_w[k * 128 + c] : 0.f;
        __nv_bfloat16 h = __float2bfloat16(v);
        __nv_bfloat16 l = __float2bfloat16(v - __bfloat162float(h));
        int phys = k * 256 + ((c * 2) ^ ((k & 7) << 4));
        *(__nv_bfloat16*)(smem + W_HI + phys) = h;
        *(__nv_bfloat16*)(smem + W_LO + phys) = l;
    }

    float acc2[8][4];
#pragma unroll
    for (int i = 0; i < 8; ++i)
#pragma unroll
        for (int j = 0; j < 4; ++j) acc2[i][j] = 0.f;
    float asum_[8][2];
#pragma unroll
    for (int i = 0; i < 8; ++i) { asum_[i][0] = 0.f; asum_[i][1] = 0.f; }

    const float* xb = x + (long)n * C_ * T_;
    const int mcol1 = 32 * w;           // GEMM1 A col byte (t = 16w)
    const int mcol2 = 32 * (w >> 1);    // GEMM2 A col byte (clusters)
    const int nh2   = 64 * (w & 1);     // GEMM2 channel half

    for (int tile = sl; tile < TILES_; tile += SL_) {
        __syncthreads();   // protect xs/soft/sninv from previous consumers
        const int t0g = tile * TT_;

        // ---- load + hi/lo convert + norms partials ----
        {
            float sqv[4] = {0.f, 0.f, 0.f, 0.f};
#pragma unroll
            for (int ci = 0; ci < 16; ++ci) {
                int c = 16 * w + ci;
                float4 v = *(const float4*)(xb + (long)c * T_ + t0g + 4 * lane);
                sqv[0] += v.x * v.x; sqv[1] += v.y * v.y;
                sqv[2] += v.z * v.z; sqv[3] += v.w * v.w;
                uint32_t hw0, lw0, hw1, lw1;
                hilo2(v.x, v.y, hw0, lw0);
                hilo2(v.z, v.w, hw1, lw1);
                int phys = c * 256 + ((8 * lane) ^ ((c & 7) << 4));
                *(uint2*)(smem + XS_HI + phys) = make_uint2(hw0, hw1);
                *(uint2*)(smem + XS_LO + phys) = make_uint2(lw0, lw1);
            }
            *(float4*)(nrmp + w * 128 + 4 * lane) = make_float4(sqv[0], sqv[1], sqv[2], sqv[3]);
        }
        __syncthreads();
        if (tid < 128) {
            float s = 0.f;
#pragma unroll
            for (int ww = 0; ww < 8; ++ww) s += nrmp[ww * 128 + tid];
            sninv_s[tid] = 1.f / fmaxf(sqrtf(s), EPSF);
        }
        __syncthreads();

        // ---- GEMM1: lg[t][kc] = sum_c x[t][c] W[kc][c], warp w owns t 16w..16w+15 ----
        float acc1[10][4];
#pragma unroll
        for (int i = 0; i < 10; ++i)
#pragma unroll
            for (int j = 0; j < 4; ++j) acc1[i][j] = 0.f;

#pragma unroll
        for (int kk = 0; kk < 8; ++kk) {
            uint32_t ah[4], al[4];
            ldsm4t(ldsm_addr(sb + XS_HI, 16 * kk, mcol1, 256, lane), ah);
            ldsm4t(ldsm_addr(sb + XS_LO, 16 * kk, mcol1, 256, lane), al);
#pragma unroll
            for (int np = 0; np < 5; ++np) {
                uint32_t bh[4], bl[4];
                ldsm4(ldsm_addr(sb + W_HI, 16 * np, 32 * kk, 256, lane), bh);
                ldsm4(ldsm_addr(sb + W_LO, 16 * np, 32 * kk, 256, lane), bl);
                mma16816(acc1[2 * np],     ah, bh);
                mma16816(acc1[2 * np + 1], ah, bh + 2);
                mma16816(acc1[2 * np],     al, bh);
                mma16816(acc1[2 * np + 1], al, bh + 2);
                mma16816(acc1[2 * np],     ah, bl);
                mma16816(acc1[2 * np + 1], ah, bl + 2);
            }
        }

        // ---- softmax over kc (rows: tA = 16w+q, tB = tA+8); ghosts 64..72, mask k=72 ----
        {
            const int tA = 16 * w + q, tB = tA + 8;
            const float ninvA = sninv_s[tA], ninvB = sninv_s[tB];
            float mA = -1e30f, mB = -1e30f;
#pragma unroll
            for (int nn = 0; nn < 9; ++nn) {
                mA = fmaxf(mA, fmaxf(acc1[nn][0], acc1[nn][1]));
                mB = fmaxf(mB, fmaxf(acc1[nn][2], acc1[nn][3]));
            }
            if (qk == 0) { mA = fmaxf(mA, acc1[9][0]); mB = fmaxf(mB, acc1[9][2]); }
            mA = fmaxf(mA, __shfl_xor_sync(~0u, mA, 1));
            mA = fmaxf(mA, __shfl_xor_sync(~0u, mA, 2));
            mB = fmaxf(mB, __shfl_xor_sync(~0u, mB, 1));
            mB = fmaxf(mB, __shfl_xor_sync(~0u, mB, 2));

            float sA = 0.f, sB = 0.f;
#pragma unroll
            for (int nn = 0; nn < 9; ++nn) {
                acc1[nn][0] = __expf((acc1[nn][0] - mA) * ninvA); sA += acc1[nn][0];
                acc1[nn][1] = __expf((acc1[nn][1] - mA) * ninvA); sA += acc1[nn][1];
                acc1[nn][2] = __expf((acc1[nn][2] - mB) * ninvB); sB += acc1[nn][2];
                acc1[nn][3] = __expf((acc1[nn][3] - mB) * ninvB); sB += acc1[nn][3];
            }
            if (qk == 0) {
                sA += __expf((acc1[9][0] - mA) * ninvA);
                sB += __expf((acc1[9][2] - mB) * ninvB);
            }
            sA += __shfl_xor_sync(~0u, sA, 1); sA += __shfl_xor_sync(~0u, sA, 2);
            sB += __shfl_xor_sync(~0u, sB, 1); sB += __shfl_xor_sync(~0u, sB, 2);
            const float isA = 1.f / sA, isB = 1.f / sB;

#pragma unroll
            for (int nn = 0; nn < 8; ++nn) {
                float s0 = acc1[nn][0] * isA, s1 = acc1[nn][1] * isA;
                float s2 = acc1[nn][2] * isB, s3 = acc1[nn][3] * isB;
                asum_[nn][0] += s0 + s2;
                asum_[nn][1] += s1 + s3;
                uint32_t hwA, lwA, hwB, lwB;
                hilo2(s0 * ninvA, s1 * ninvA, hwA, lwA);
                hilo2(s2 * ninvB, s3 * ninvB, hwB, lwB);
                int cbyte = 16 * nn + 4 * qk;
                int pA = tA * 128 + (cbyte ^ ((tA & 7) << 4));
                int pB = tB * 128 + (cbyte ^ ((tB & 7) << 4));
                *(uint32_t*)(smem + SF_HI + pA) = hwA;
                *(uint32_t*)(smem + SF_LO + pA) = lwA;
                *(uint32_t*)(smem + SF_HI + pB) = hwB;
                *(uint32_t*)(smem + SF_LO + pB) = lwB;
            }
        }
        __syncthreads();

        // ---- GEMM2: vlad[kc][c] += soft_scaled[kc][t] x[c][t]^T ----
#pragma unroll
        for (int kk = 0; kk < 8; ++kk) {
            uint32_t ah[4], al[4];
            ldsm4t(ldsm_addr(sb + SF_HI, 16 * kk, mcol2, 128, lane), ah);
            ldsm4t(ldsm_addr(sb + SF_LO, 16 * kk, mcol2, 128, lane), al);
#pragma unroll
            for (int np = 0; np < 4; ++np) {
                uint32_t bh[4], bl[4];
                ldsm4(ldsm_addr(sb + XS_HI, nh2 + 16 * np, 32 * kk, 256, lane), bh);
                ldsm4(ldsm_addr(sb + XS_LO, nh2 + 16 * np, 32 * kk, 256, lane), bl);
                mma16816(acc2[2 * np],     ah, bh);
                mma16816(acc2[2 * np + 1], ah, bh + 2);
                mma16816(acc2[2 * np],     al, bh);
                mma16816(acc2[2 * np + 1], al, bh + 2);
                mma16816(acc2[2 * np],     ah, bl);
                mma16816(acc2[2 * np + 1], ah, bl + 2);
            }
        }
    }

    // ---- asum reduce: lanes same qk across quads, then cross-warp via smem ----
    __syncthreads();
#pragma unroll
    for (int nn = 0; nn < 8; ++nn) {
#pragma unroll
        for (int e = 0; e < 2; ++e) {
            float v = asum_[nn][e];
            v += __shfl_xor_sync(~0u, v, 4);
            v += __shfl_xor_sync(~0u, v, 8);
            v += __shfl_xor_sync(~0u, v, 16);
            if (lane < 4) asw[w * 64 + 8 * nn + 2 * lane + e] = v;
        }
    }
    __syncthreads();
    if (tid < 64) {
        float s = 0.f;
#pragma unroll
        for (int ww = 0; ww < 8; ++ww) s += asw[ww * 64 + tid];
        g_asum_part[((long)(sl * N_ + n)) * K_ + tid] = s;
    }

    // ---- drain acc2: warp w -> clusters 16(w>>1)+row, channels 64(w&1).. ----
    {
        const int kA = 16 * (w >> 1) + q, kB = kA + 8;
        float* gp = g_vlad_part + ((long)(sl * N_ + n)) * K_ * C_;
#pragma unroll
        for (int nn = 0; nn < 8; ++nn) {
            int c = nh2 + 8 * nn + 2 * qk;
            *(float2*)(gp + (long)kA * C_ + c) = make_float2(acc2[nn][0], acc2[nn][1]);
            *(float2*)(gp + (long)kB * C_ + c) = make_float2(acc2[nn][2], acc2[nn][3]);
        }
    }
}

// ---- Reduce: one CTA per (n,k) ----
__global__ __launch_bounds__(128)
void vlad_reduce(const float* __restrict__ centroids,
                 const float* __restrict__ cwts,
                 float* __restrict__ out) {
    const int k = blockIdx.x, n = blockIdx.y;
    const int tid = threadIdx.x;

    __shared__ float red[128];
    __shared__ float scw;

    float v = 0.f;
    const float* base = g_vlad_part + (long)n * K_ * C_ + (long)k * C_ + tid;
    const long str = (long)N_ * K_ * C_;
#pragma unroll
    for (int sl = 0; sl < SL_; ++sl) v += base[sl * str];

    red[tid] = (tid < SL_) ? g_asum_part[((long)(tid * N_ + n)) * K_ + k] : 0.f;
    if (tid == 0) {
        float s = 0.f;
        for (int kk = 0; kk < K_; ++kk) s += cwts[kk] * cwts[kk];
        scw = 1.f / fmaxf(sqrtf(s), EPSF);
    }
    __syncthreads();
#pragma unroll
    for (int s = 64; s > 0; s >>= 1) { if (tid < s) red[tid] += red[tid + s]; __syncthreads(); }
    const float asumv = red[0];
    __syncthreads();

    v -= asumv * centroids[k * C_ + tid];

    red[tid] = v * v;
    __syncthreads();
#pragma unroll
    for (int s = 64; s > 0; s >>= 1) { if (tid < s) red[tid] += red[tid + s]; __syncthreads(); }
    const float ssq = red[0];

    const float scale = (1.f / fmaxf(sqrtf(ssq), EPSF)) * cwts[k] * scw;
    out[(long)n * K_ * C_ + (long)k * C_ + tid] = v * scale;
    if (tid == 0) g_knorm[n * K_ + k] = ssq * scale * scale;
}

__global__ __launch_bounds__(256)
void vlad_finalize(float* __restrict__ out) {
    const int n = blockIdx.x, tid = threadIdx.x;
    __shared__ float sginv;
    if (tid == 0) {
        float g = 0.f;
        for (int k = 0; k < K_; ++k) g += g_knorm[n * K_ + k];
        sginv = 1.f / fmaxf(sqrtf(g), EPSF);
    }
    __syncthreads();
    const float gi = sginv;
    float4* p = (float4*)(out + (long)n * K_ * C_);
    for (int i = tid; i < (K_ * C_) / 4; i += 256) {
        float4 v = p[i];
        v.x *= gi; v.y *= gi; v.z *= gi; v.w *= gi;
        p[i] = v;
    }
}

extern "C" void kernel_launch(void* const* d_in, const int* in_sizes, int n_in,
                              void* d_out, int out_size) {
    const float* x      = (const float*)d_in[0];
    const float* conv_w = (const float*)d_in[1];
    const float* cent   = (const float*)d_in[2];
    const float* cwts   = (const float*)d_in[3];
    float* out = (float*)d_out;

    cudaFuncSetAttribute(vlad_mma, cudaFuncAttributeMaxDynamicSharedMemorySize, SMEM_SZ);
    vlad_mma<<<dim3(N_, SL_), 256, SMEM_SZ>>>(x, conv_w);
    vlad_reduce<<<dim3(K_, N_), 128>>>(cent, cwts, out);
    vlad_finalize<<<N_, 256>>>(out);
}